// round 1
// baseline (speedup 1.0000x reference)
#include <cuda_runtime.h>
#include <math.h>

#define BATCH 32
#define MAXPV 50
#define RULENUM 256
#define ED 128
#define NPV (BATCH*MAXPV)   // 1600

// ---------------- scratch (device globals; no allocations allowed) ----------
__device__ float g_pemb[NPV*ED];
__device__ float g_vemb[NPV*ED];
__device__ float g_remb[RULENUM*ED];
__device__ float g_propemb[RULENUM*ED];
__device__ float g_pa[NPV*ED];
__device__ float g_pb[NPV*ED];
__device__ float g_pc[NPV*ED];
__device__ float g_ra[RULENUM*ED];
__device__ float g_rb[RULENUM*ED];
__device__ float g_rc[RULENUM*ED];
__device__ float g_propa[RULENUM*ED];
__device__ float g_rulemask[RULENUM];
__device__ float g_regpart[RULENUM];
__device__ float g_scores[BATCH*RULENUM];

// ---------------- kernel 1: gather + l2 normalize ---------------------------
// rows: [0,1600) p_emb, [1600,3200) v_emb, [3200,3456) r_emb, [3456,3712) prop_emb
__global__ void norm_gather_kernel(const int* __restrict__ prop,
                                   const int* __restrict__ val,
                                   const float* __restrict__ ent,
                                   const float* __restrict__ rule)
{
    int row = blockIdx.x;
    int k = threadIdx.x;
    const float* src; float* dst;
    if (row < NPV)            { src = ent + (size_t)prop[row]*ED;              dst = g_pemb + row*ED; }
    else if (row < 2*NPV)     { int t=row-NPV;   src = ent + (size_t)val[t]*ED; dst = g_vemb + t*ED; }
    else if (row < 2*NPV+256) { int t=row-2*NPV; src = rule + t*ED;            dst = g_remb + t*ED; }
    else                      { int t=row-2*NPV-256; src = ent + (size_t)t*ED; dst = g_propemb + t*ED; }

    float x = src[k];
    float s = x*x;
    #pragma unroll
    for (int o=16;o>0;o>>=1) s += __shfl_xor_sync(0xffffffffu, s, o);
    __shared__ float ws[4];
    if ((k&31)==0) ws[k>>5] = s;
    __syncthreads();
    float tot = ws[0]+ws[1]+ws[2]+ws[3];
    float n = fmaxf(sqrtf(tot), 1e-12f);
    dst[k] = x / n;
}

// ---------------- kernel 2: all small 128x128 GEMMs -------------------------
// jobs by blockIdx.x:
// [0,1600) pa=pemb@fc1[:128] ; [1600,3200) pb ; [3200,4800) pc ;
// [4800,5056) ra=remb@fc1[128:]+b1 ; [5056,5312) rb ; [5312,5568) rc ;
// [5568,5824) prop_a=propemb@fc1[:128]
__global__ void small_gemm_kernel(const float* __restrict__ fc1w, const float* __restrict__ fc1b,
                                  const float* __restrict__ fc2w, const float* __restrict__ fc2b,
                                  const float* __restrict__ fc3w, const float* __restrict__ fc3b)
{
    int row = blockIdx.x, k = threadIdx.x;
    const float *in, *W; const float* bias = nullptr; float* out;
    if (row < 1600)      { in=g_pemb+row*ED;            W=fc1w;        out=g_pa+row*ED; }
    else if (row < 3200) { int t=row-1600; in=g_pemb+t*ED; W=fc2w;     out=g_pb+t*ED; }
    else if (row < 4800) { int t=row-3200; in=g_pemb+t*ED; W=fc3w;     out=g_pc+t*ED; }
    else if (row < 5056) { int t=row-4800; in=g_remb+t*ED; W=fc1w+ED*ED; bias=fc1b; out=g_ra+t*ED; }
    else if (row < 5312) { int t=row-5056; in=g_remb+t*ED; W=fc2w+ED*ED; bias=fc2b; out=g_rb+t*ED; }
    else if (row < 5568) { int t=row-5312; in=g_remb+t*ED; W=fc3w+ED*ED; bias=fc3b; out=g_rc+t*ED; }
    else                 { int t=row-5568; in=g_propemb+t*ED; W=fc1w;  out=g_propa+t*ED; }

    __shared__ float inrow[ED];
    inrow[k] = in[k];
    __syncthreads();
    float acc = bias ? bias[k] : 0.f;
    #pragma unroll 8
    for (int i=0;i<ED;i++) acc = fmaf(inrow[i], __ldg(W + i*ED + k), acc);
    out[k] = acc;
}

// ---------------- kernel 3: pi matrix -> rule_mask + reg partials -----------
// grid: 256 blocks (one per rule), 256 threads (8 warps x 32 props each)
__global__ void pi_kernel(const float* __restrict__ fc4w, const float* __restrict__ fc4b)
{
    int r = blockIdx.x;
    int tid = threadIdx.x, lane = tid&31, w = tid>>5;
    __shared__ float rarow[ED], f4s[ED];
    if (tid < ED){ rarow[tid] = g_ra[r*ED+tid]; f4s[tid] = fc4w[tid]; }
    __syncthreads();
    float fb4 = fc4b[0];
    float mask_s = 0.f, reg_s = 0.f;
    for (int pp=0; pp<32; pp++){
        int p = w*32 + pp;
        float s = 0.f;
        #pragma unroll
        for (int q=0;q<4;q++){
            int i = lane*4 + q;
            float h = fmaxf(g_propa[p*ED + i] + rarow[i], 0.f);
            s = fmaf(h, f4s[i], s);
        }
        #pragma unroll
        for (int o=16;o>0;o>>=1) s += __shfl_xor_sync(0xffffffffu, s, o);
        if (lane==0){
            float piv = 1.f/(1.f+expf(-(s+fb4)));
            if (piv > 0.5f) mask_s += piv;
            float diag = (r==p) ? 1.f : 0.f;
            float rv = piv*diag + (1.f-piv)*(1.f-diag);
            reg_s += -logf(rv + 1e-8f) * ((1.f-diag) + diag*(float)RULENUM);
        }
    }
    __shared__ float ms[8], rs[8];
    if (lane==0){ ms[w]=mask_s; rs[w]=reg_s; }
    __syncthreads();
    if (tid==0){
        float m=0.f, rg=0.f;
        #pragma unroll
        for (int i=0;i<8;i++){ m+=ms[i]; rg+=rs[i]; }
        g_rulemask[r] = m + 1.f;
        g_regpart[r]  = rg;
    }
}

// ---------------- kernel 4: main (b,r) scoring -------------------------------
// One 128-thread block per (r,b). Thread k owns output dim k.
// fc6 column k lives in registers (128 regs) -> FFMA-issue bound, not LDS bound.
__global__ void __launch_bounds__(128, 2) main_kernel(
    const int* __restrict__ samemask, const int* __restrict__ padmask,
    const float* __restrict__ fc4w, const float* __restrict__ fc4b,
    const float* __restrict__ fc5w, const float* __restrict__ fc5b,
    const float* __restrict__ fc6w, const float* __restrict__ fc6b)
{
    int r = blockIdx.x, b = blockIdx.y;
    int k = threadIdx.x, lane = k&31, w = k>>5;

    __shared__ __align__(16) float h3sh[2][ED];
    __shared__ float red[4][4];

    float Wreg[ED];
    #pragma unroll
    for (int i=0;i<ED;i++) Wreg[i] = fc6w[i*ED + k];

    float ra_k = g_ra[r*ED+k], rb_k = g_rb[r*ED+k], rc_k = g_rc[r*ED+k];
    float f4 = fc4w[k], f5 = fc5w[k], b6 = fc6b[k];
    float fb4 = fc4b[0], fb5 = fc5b[0];
    float acc = 0.0f;

    for (int j=0;j<MAXPV;j++){
        int base = (b*MAXPV + j)*ED + k;
        float pa = g_pa[base], pb = g_pb[base], pc = g_pc[base], v = g_vemb[base];
        float h1 = fmaxf(pa + ra_k, 0.f);
        float h2 = fmaxf(pb + rb_k, 0.f);
        float h3 = fmaxf(pc + rc_k, 0.f);
        float* cur = h3sh[j & 1];
        cur[k] = h3;
        float r0 = h1*f4, r1 = h2*f5;
        __syncthreads();                       // cur published; prev-iter red consumed

        float y = b6;
        const float4* h4p = reinterpret_cast<const float4*>(cur);
        #pragma unroll
        for (int i4=0;i4<ED/4;i4++){
            float4 h4 = h4p[i4];
            y = fmaf(h4.x, Wreg[4*i4+0], y);
            y = fmaf(h4.y, Wreg[4*i4+1], y);
            y = fmaf(h4.z, Wreg[4*i4+2], y);
            y = fmaf(h4.w, Wreg[4*i4+3], y);
        }
        float r2 = y*y, r3 = y*v;
        #pragma unroll
        for (int o=16;o>0;o>>=1){
            r0 += __shfl_xor_sync(0xffffffffu, r0, o);
            r1 += __shfl_xor_sync(0xffffffffu, r1, o);
            r2 += __shfl_xor_sync(0xffffffffu, r2, o);
            r3 += __shfl_xor_sync(0xffffffffu, r3, o);
        }
        if (lane==0){ red[0][w]=r0; red[1][w]=r1; red[2][w]=r2; red[3][w]=r3; }
        __syncthreads();
        if (k==0){
            float s1d = red[0][0]+red[0][1]+red[0][2]+red[0][3];
            float pd  = red[1][0]+red[1][1]+red[1][2]+red[1][3];
            float yn2 = red[2][0]+red[2][1]+red[2][2]+red[2][3];
            float ydv = red[3][0]+red[3][1]+red[3][2]+red[3][3];
            float s1 = 1.f/(1.f+expf(-(s1d+fb4)));
            float p  = 1.f/(1.f+expf(-(pd +fb5)));
            float yn = sqrtf(yn2);
            float cosv = ydv / fmaxf(yn, 1e-8f);   // v_emb is unit-norm; gv = y/||y||
            float s2 = 0.5f*cosv + 0.5f;
            float sc = p + (1.f-p)*s2;
            sc = (samemask[b*MAXPV+j]==1) ? (s1*sc) : (1.f - s1);
            sc *= (float)padmask[b*MAXPV+j];
            if (!(s1 > 0.5f)) sc = 0.f;
            acc += sc;
        }
    }
    if (k==0) g_scores[b*RULENUM + r] = acc / g_rulemask[r];
}

// ---------------- kernel 5: deterministic finalize ---------------------------
__global__ void finalize_kernel(float* __restrict__ out, int out_size)
{
    int tid = threadIdx.x, lane = tid&31, w = tid>>5;  // 256 threads, 8 warps
    // reg_logits = sum(g_regpart)/65536
    float rg = g_regpart[tid];
    #pragma unroll
    for (int o=16;o>0;o>>=1) rg += __shfl_xor_sync(0xffffffffu, rg, o);
    __shared__ float rs[8];
    if (lane==0) rs[w] = rg;
    __syncthreads();
    if (tid==0 && out_size > BATCH){
        float t=0.f;
        #pragma unroll
        for (int i=0;i<8;i++) t += rs[i];
        out[BATCH] = t / (float)(RULENUM*RULENUM);
    }
    // pooledscore[b] = max_r scores[b][r]; warp w handles b = 4w..4w+3
    #pragma unroll
    for (int q=0;q<4;q++){
        int b = w*4 + q;
        float m = -1e30f;
        for (int c=lane;c<RULENUM;c+=32) m = fmaxf(m, g_scores[b*RULENUM+c]);
        #pragma unroll
        for (int o=16;o>0;o>>=1) m = fmaxf(m, __shfl_xor_sync(0xffffffffu, m, o));
        if (lane==0 && b < out_size) out[b] = m;
    }
}

// ---------------- launch -----------------------------------------------------
extern "C" void kernel_launch(void* const* d_in, const int* in_sizes, int n_in,
                              void* d_out, int out_size)
{
    const int*   prop = (const int*)d_in[0];
    const int*   val  = (const int*)d_in[1];
    const int*   same = (const int*)d_in[2];
    const int*   pad  = (const int*)d_in[3];
    const float* rule = (const float*)d_in[4];
    const float* ent  = (const float*)d_in[5];
    const float* fc1w = (const float*)d_in[6];
    const float* fc1b = (const float*)d_in[7];
    const float* fc2w = (const float*)d_in[8];
    const float* fc2b = (const float*)d_in[9];
    const float* fc3w = (const float*)d_in[10];
    const float* fc3b = (const float*)d_in[11];
    const float* fc4w = (const float*)d_in[12];
    const float* fc4b = (const float*)d_in[13];
    const float* fc5w = (const float*)d_in[14];
    const float* fc5b = (const float*)d_in[15];
    const float* fc6w = (const float*)d_in[16];
    const float* fc6b = (const float*)d_in[17];

    norm_gather_kernel<<<2*NPV + 2*RULENUM, 128>>>(prop, val, ent, rule);
    small_gemm_kernel<<<3*NPV + 4*RULENUM, 128>>>(fc1w, fc1b, fc2w, fc2b, fc3w, fc3b);
    pi_kernel<<<RULENUM, 256>>>(fc4w, fc4b);
    main_kernel<<<dim3(RULENUM, BATCH), 128>>>(same, pad, fc4w, fc4b, fc5w, fc5b, fc6w, fc6b);
    finalize_kernel<<<1, 256>>>((float*)d_out, out_size);
}

// round 2
// speedup vs baseline: 1.4094x; 1.4094x over previous
#include <cuda_runtime.h>
#include <math.h>

#define BATCH 32
#define MAXPV 50
#define RULENUM 256
#define ED 128
#define NPV (BATCH*MAXPV)   // 1600

#define FMA2(acc,a,bb) asm("fma.rn.f32x2 %0, %1, %2, %0;" : "+l"(acc) : "l"(a), "l"(bb))
#define ADD2(d,a,bb)   asm("add.rn.f32x2 %0, %1, %2;" : "=l"(d) : "l"(a), "l"(bb))
#define PACK2(d,lo,hi) asm("mov.b64 %0, {%1,%2};" : "=l"(d) : "f"(lo), "f"(hi))
#define UNPACK2(lo,hi,s) asm("mov.b64 {%0,%1}, %2;" : "=f"(lo), "=f"(hi) : "l"(s))

// ---------------- scratch (device globals; no allocations allowed) ----------
__device__ float g_pemb[NPV*ED];
__device__ float g_vemb[NPV*ED];
__device__ float g_remb[RULENUM*ED];
__device__ float g_propemb[RULENUM*ED];
__device__ float g_pa[NPV*ED];
__device__ float g_pb[NPV*ED];
__device__ float g_pc[NPV*ED];
__device__ float g_ra[RULENUM*ED];
__device__ float g_rb[RULENUM*ED];
__device__ float g_rc[RULENUM*ED];
__device__ float g_propa[RULENUM*ED];
__device__ float g_rulemask[RULENUM];
__device__ float g_regpart[RULENUM];
__device__ float g_scores[BATCH*RULENUM];

// ---------------- kernel 1: gather + l2 normalize ---------------------------
__global__ void norm_gather_kernel(const int* __restrict__ prop,
                                   const int* __restrict__ val,
                                   const float* __restrict__ ent,
                                   const float* __restrict__ rule)
{
    int row = blockIdx.x;
    int k = threadIdx.x;
    const float* src; float* dst;
    if (row < NPV)            { src = ent + (size_t)prop[row]*ED;              dst = g_pemb + row*ED; }
    else if (row < 2*NPV)     { int t=row-NPV;   src = ent + (size_t)val[t]*ED; dst = g_vemb + t*ED; }
    else if (row < 2*NPV+256) { int t=row-2*NPV; src = rule + t*ED;            dst = g_remb + t*ED; }
    else                      { int t=row-2*NPV-256; src = ent + (size_t)t*ED; dst = g_propemb + t*ED; }

    float x = src[k];
    float s = x*x;
    #pragma unroll
    for (int o=16;o>0;o>>=1) s += __shfl_xor_sync(0xffffffffu, s, o);
    __shared__ float ws[4];
    if ((k&31)==0) ws[k>>5] = s;
    __syncthreads();
    float tot = ws[0]+ws[1]+ws[2]+ws[3];
    float n = fmaxf(sqrtf(tot), 1e-12f);
    dst[k] = x / n;
}

// ---------------- kernel 2: all small 128x128 GEMMs -------------------------
__global__ void small_gemm_kernel(const float* __restrict__ fc1w, const float* __restrict__ fc1b,
                                  const float* __restrict__ fc2w, const float* __restrict__ fc2b,
                                  const float* __restrict__ fc3w, const float* __restrict__ fc3b)
{
    int row = blockIdx.x, k = threadIdx.x;
    const float *in, *W; const float* bias = nullptr; float* out;
    if (row < 1600)      { in=g_pemb+row*ED;            W=fc1w;        out=g_pa+row*ED; }
    else if (row < 3200) { int t=row-1600; in=g_pemb+t*ED; W=fc2w;     out=g_pb+t*ED; }
    else if (row < 4800) { int t=row-3200; in=g_pemb+t*ED; W=fc3w;     out=g_pc+t*ED; }
    else if (row < 5056) { int t=row-4800; in=g_remb+t*ED; W=fc1w+ED*ED; bias=fc1b; out=g_ra+t*ED; }
    else if (row < 5312) { int t=row-5056; in=g_remb+t*ED; W=fc2w+ED*ED; bias=fc2b; out=g_rb+t*ED; }
    else if (row < 5568) { int t=row-5312; in=g_remb+t*ED; W=fc3w+ED*ED; bias=fc3b; out=g_rc+t*ED; }
    else                 { int t=row-5568; in=g_propemb+t*ED; W=fc1w;  out=g_propa+t*ED; }

    __shared__ float inrow[ED];
    inrow[k] = in[k];
    __syncthreads();
    float acc = bias ? bias[k] : 0.f;
    #pragma unroll 8
    for (int i=0;i<ED;i++) acc = fmaf(inrow[i], __ldg(W + i*ED + k), acc);
    out[k] = acc;
}

// ---------------- kernel 3: pi matrix -> rule_mask + reg partials -----------
__global__ void pi_kernel(const float* __restrict__ fc4w, const float* __restrict__ fc4b)
{
    int r = blockIdx.x;
    int tid = threadIdx.x, lane = tid&31, w = tid>>5;
    __shared__ float rarow[ED], f4s[ED];
    if (tid < ED){ rarow[tid] = g_ra[r*ED+tid]; f4s[tid] = fc4w[tid]; }
    __syncthreads();
    float fb4 = fc4b[0];
    float mask_s = 0.f, reg_s = 0.f;
    for (int pp=0; pp<32; pp++){
        int p = w*32 + pp;
        float s = 0.f;
        #pragma unroll
        for (int q=0;q<4;q++){
            int i = lane*4 + q;
            float h = fmaxf(g_propa[p*ED + i] + rarow[i], 0.f);
            s = fmaf(h, f4s[i], s);
        }
        #pragma unroll
        for (int o=16;o>0;o>>=1) s += __shfl_xor_sync(0xffffffffu, s, o);
        if (lane==0){
            float piv = 1.f/(1.f+expf(-(s+fb4)));
            if (piv > 0.5f) mask_s += piv;
            float diag = (r==p) ? 1.f : 0.f;
            float rv = piv*diag + (1.f-piv)*(1.f-diag);
            reg_s += -logf(rv + 1e-8f) * ((1.f-diag) + diag*(float)RULENUM);
        }
    }
    __shared__ float ms[8], rs[8];
    if (lane==0){ ms[w]=mask_s; rs[w]=reg_s; }
    __syncthreads();
    if (tid==0){
        float m=0.f, rg=0.f;
        #pragma unroll
        for (int i=0;i<8;i++){ m+=ms[i]; rg+=rs[i]; }
        g_rulemask[r] = m + 1.f;
        g_regpart[r]  = rg;
    }
}

// ---------------- kernel 4: main (b,r) scoring -------------------------------
// One 128-thread block per (r,b). Thread k owns output dim k.
// fc6 column k packed into 64 f32x2 registers; dot via fma.rn.f32x2 with
// 4 independent accumulator chains. One syncthreads per j (double buffer).
// All per-j scalar epilogues (sigmoid/score) deferred and done in parallel.
__global__ void __launch_bounds__(128, 2) main_kernel(
    const int* __restrict__ samemask, const int* __restrict__ padmask,
    const float* __restrict__ fc4w, const float* __restrict__ fc4b,
    const float* __restrict__ fc5w, const float* __restrict__ fc5b,
    const float* __restrict__ fc6w, const float* __restrict__ fc6b)
{
    int r = blockIdx.x, b = blockIdx.y;
    int k = threadIdx.x, lane = k&31, w = k>>5;

    __shared__ __align__(16) float h3sh[2][ED];
    __shared__ float sred[MAXPV][4][4];
    __shared__ float scj[MAXPV];

    // pack fc6 column k into f32x2 registers: Wp[i] = (fc6w[2i][k], fc6w[2i+1][k])
    unsigned long long Wp[ED/2];
    #pragma unroll
    for (int i=0;i<ED/2;i++){
        float lo = fc6w[(2*i)*ED + k];
        float hi = fc6w[(2*i+1)*ED + k];
        PACK2(Wp[i], lo, hi);
    }

    float ra_k = g_ra[r*ED+k], rb_k = g_rb[r*ED+k], rc_k = g_rc[r*ED+k];
    float f4 = fc4w[k], f5 = fc5w[k], b6 = fc6b[k];

    for (int j=0;j<MAXPV;j++){
        int base = (b*MAXPV + j)*ED + k;
        float pa = g_pa[base], pb = g_pb[base], pc = g_pc[base], v = g_vemb[base];
        float h1 = fmaxf(pa + ra_k, 0.f);
        float h2 = fmaxf(pb + rb_k, 0.f);
        float h3 = fmaxf(pc + rc_k, 0.f);
        h3sh[j & 1][k] = h3;
        float r0 = h1*f4, r1 = h2*f5;
        __syncthreads();   // publish h3sh[j&1]; also fences buffer reuse (j-2)

        const unsigned long long* hp =
            reinterpret_cast<const unsigned long long*>(h3sh[j & 1]);
        unsigned long long a0=0ull, a1=0ull, a2=0ull, a3=0ull;
        #pragma unroll
        for (int i=0;i<ED/2;i+=4){
            FMA2(a0, hp[i+0], Wp[i+0]);
            FMA2(a1, hp[i+1], Wp[i+1]);
            FMA2(a2, hp[i+2], Wp[i+2]);
            FMA2(a3, hp[i+3], Wp[i+3]);
        }
        unsigned long long s01, s23, s64;
        ADD2(s01, a0, a1); ADD2(s23, a2, a3); ADD2(s64, s01, s23);
        float ylo, yhi; UNPACK2(ylo, yhi, s64);
        float y = b6 + (ylo + yhi);

        float r2 = y*y, r3 = y*v;
        #pragma unroll
        for (int o=16;o>0;o>>=1){
            r0 += __shfl_xor_sync(0xffffffffu, r0, o);
            r1 += __shfl_xor_sync(0xffffffffu, r1, o);
            r2 += __shfl_xor_sync(0xffffffffu, r2, o);
            r3 += __shfl_xor_sync(0xffffffffu, r3, o);
        }
        if (lane==0){
            sred[j][0][w]=r0; sred[j][1][w]=r1; sred[j][2][w]=r2; sred[j][3][w]=r3;
        }
    }
    __syncthreads();

    float fb4 = fc4b[0], fb5 = fc5b[0];
    if (k < MAXPV){
        float s1d = sred[k][0][0]+sred[k][0][1]+sred[k][0][2]+sred[k][0][3];
        float pd  = sred[k][1][0]+sred[k][1][1]+sred[k][1][2]+sred[k][1][3];
        float yn2 = sred[k][2][0]+sred[k][2][1]+sred[k][2][2]+sred[k][2][3];
        float ydv = sred[k][3][0]+sred[k][3][1]+sred[k][3][2]+sred[k][3][3];
        float s1 = 1.f/(1.f+expf(-(s1d+fb4)));
        float p  = 1.f/(1.f+expf(-(pd +fb5)));
        float yn = sqrtf(yn2);
        float cosv = ydv / fmaxf(yn, 1e-8f);   // v_emb is unit-norm; gv = y/||y||
        float s2 = 0.5f*cosv + 0.5f;
        float sc = p + (1.f-p)*s2;
        sc = (samemask[b*MAXPV+k]==1) ? (s1*sc) : (1.f - s1);
        sc *= (float)padmask[b*MAXPV+k];
        if (!(s1 > 0.5f)) sc = 0.f;
        scj[k] = sc;
    }
    __syncthreads();
    if (k < 32){
        float s = scj[k];
        if (k + 32 < MAXPV) s += scj[k+32];
        #pragma unroll
        for (int o=16;o>0;o>>=1) s += __shfl_xor_sync(0xffffffffu, s, o);
        if (k==0) g_scores[b*RULENUM + r] = s / g_rulemask[r];
    }
}

// ---------------- kernel 5: deterministic finalize ---------------------------
__global__ void finalize_kernel(float* __restrict__ out, int out_size)
{
    int tid = threadIdx.x, lane = tid&31, w = tid>>5;  // 256 threads, 8 warps
    float rg = g_regpart[tid];
    #pragma unroll
    for (int o=16;o>0;o>>=1) rg += __shfl_xor_sync(0xffffffffu, rg, o);
    __shared__ float rs[8];
    if (lane==0) rs[w] = rg;
    __syncthreads();
    if (tid==0 && out_size > BATCH){
        float t=0.f;
        #pragma unroll
        for (int i=0;i<8;i++) t += rs[i];
        out[BATCH] = t / (float)(RULENUM*RULENUM);
    }
    #pragma unroll
    for (int q=0;q<4;q++){
        int b = w*4 + q;
        float m = -1e30f;
        for (int c=lane;c<RULENUM;c+=32) m = fmaxf(m, g_scores[b*RULENUM+c]);
        #pragma unroll
        for (int o=16;o>0;o>>=1) m = fmaxf(m, __shfl_xor_sync(0xffffffffu, m, o));
        if (lane==0 && b < out_size) out[b] = m;
    }
}

// ---------------- launch -----------------------------------------------------
extern "C" void kernel_launch(void* const* d_in, const int* in_sizes, int n_in,
                              void* d_out, int out_size)
{
    const int*   prop = (const int*)d_in[0];
    const int*   val  = (const int*)d_in[1];
    const int*   same = (const int*)d_in[2];
    const int*   pad  = (const int*)d_in[3];
    const float* rule = (const float*)d_in[4];
    const float* ent  = (const float*)d_in[5];
    const float* fc1w = (const float*)d_in[6];
    const float* fc1b = (const float*)d_in[7];
    const float* fc2w = (const float*)d_in[8];
    const float* fc2b = (const float*)d_in[9];
    const float* fc3w = (const float*)d_in[10];
    const float* fc3b = (const float*)d_in[11];
    const float* fc4w = (const float*)d_in[12];
    const float* fc4b = (const float*)d_in[13];
    const float* fc5w = (const float*)d_in[14];
    const float* fc5b = (const float*)d_in[15];
    const float* fc6w = (const float*)d_in[16];
    const float* fc6b = (const float*)d_in[17];

    norm_gather_kernel<<<2*NPV + 2*RULENUM, 128>>>(prop, val, ent, rule);
    small_gemm_kernel<<<3*NPV + 4*RULENUM, 128>>>(fc1w, fc1b, fc2w, fc2b, fc3w, fc3b);
    pi_kernel<<<RULENUM, 256>>>(fc4w, fc4b);
    main_kernel<<<dim3(RULENUM, BATCH), 128>>>(same, pad, fc4w, fc4b, fc5w, fc5b, fc6w, fc6b);
    finalize_kernel<<<1, 256>>>((float*)d_out, out_size);
}

// round 4
// speedup vs baseline: 1.9048x; 1.3515x over previous
#include <cuda_runtime.h>
#include <math.h>

#define BATCH 32
#define MAXPV 50
#define RULENUM 256
#define ED 128
#define NPV (BATCH*MAXPV)   // 1600

#define FMA2(acc,a,bb) asm("fma.rn.f32x2 %0, %1, %2, %0;" : "+l"(acc) : "l"(a), "l"(bb))
#define ADD2(d,a,bb)   asm("add.rn.f32x2 %0, %1, %2;" : "=l"(d) : "l"(a), "l"(bb))
#define PACK2(d,lo,hi) asm("mov.b64 %0, {%1,%2};" : "=l"(d) : "f"(lo), "f"(hi))
#define UNPACK2(lo,hi,s) asm("mov.b64 {%0,%1}, %2;" : "=f"(lo), "=f"(hi) : "l"(s))

// ---------------- scratch (device globals; no allocations allowed) ----------
__device__ float g_pemb[NPV*ED];
__device__ float g_vemb[NPV*ED];
__device__ float g_remb[RULENUM*ED];
__device__ float g_propemb[RULENUM*ED];
__device__ float g_pa[NPV*ED];
__device__ float g_pb[NPV*ED];
__device__ float g_pc[NPV*ED];
__device__ float g_ra[RULENUM*ED];
__device__ float g_rb[RULENUM*ED];
__device__ float g_rc[RULENUM*ED];
__device__ float g_propa[RULENUM*ED];
__device__ float g_rulemask[RULENUM];
__device__ float g_regpart[RULENUM];
__device__ float g_scores[BATCH*RULENUM];

// ---------------- kernel 1: gather + l2 normalize ---------------------------
__global__ void norm_gather_kernel(const int* __restrict__ prop,
                                   const int* __restrict__ val,
                                   const float* __restrict__ ent,
                                   const float* __restrict__ rule)
{
    int row = blockIdx.x;
    int k = threadIdx.x;
    const float* src; float* dst;
    if (row < NPV)            { src = ent + (size_t)prop[row]*ED;              dst = g_pemb + row*ED; }
    else if (row < 2*NPV)     { int t=row-NPV;   src = ent + (size_t)val[t]*ED; dst = g_vemb + t*ED; }
    else if (row < 2*NPV+256) { int t=row-2*NPV; src = rule + t*ED;            dst = g_remb + t*ED; }
    else                      { int t=row-2*NPV-256; src = ent + (size_t)t*ED; dst = g_propemb + t*ED; }

    float x = src[k];
    float s = x*x;
    #pragma unroll
    for (int o=16;o>0;o>>=1) s += __shfl_xor_sync(0xffffffffu, s, o);
    __shared__ float ws[4];
    if ((k&31)==0) ws[k>>5] = s;
    __syncthreads();
    float tot = ws[0]+ws[1]+ws[2]+ws[3];
    float n = fmaxf(sqrtf(tot), 1e-12f);
    dst[k] = x / n;
}

// ---------------- kernel 2: all small 128x128 GEMMs -------------------------
__global__ void small_gemm_kernel(const float* __restrict__ fc1w, const float* __restrict__ fc1b,
                                  const float* __restrict__ fc2w, const float* __restrict__ fc2b,
                                  const float* __restrict__ fc3w, const float* __restrict__ fc3b)
{
    int row = blockIdx.x, k = threadIdx.x;
    const float *in, *W; const float* bias = nullptr; float* out;
    if (row < 1600)      { in=g_pemb+row*ED;            W=fc1w;        out=g_pa+row*ED; }
    else if (row < 3200) { int t=row-1600; in=g_pemb+t*ED; W=fc2w;     out=g_pb+t*ED; }
    else if (row < 4800) { int t=row-3200; in=g_pemb+t*ED; W=fc3w;     out=g_pc+t*ED; }
    else if (row < 5056) { int t=row-4800; in=g_remb+t*ED; W=fc1w+ED*ED; bias=fc1b; out=g_ra+t*ED; }
    else if (row < 5312) { int t=row-5056; in=g_remb+t*ED; W=fc2w+ED*ED; bias=fc2b; out=g_rb+t*ED; }
    else if (row < 5568) { int t=row-5312; in=g_remb+t*ED; W=fc3w+ED*ED; bias=fc3b; out=g_rc+t*ED; }
    else                 { int t=row-5568; in=g_propemb+t*ED; W=fc1w;  out=g_propa+t*ED; }

    __shared__ float inrow[ED];
    inrow[k] = in[k];
    __syncthreads();
    float acc = bias ? bias[k] : 0.f;
    #pragma unroll 8
    for (int i=0;i<ED;i++) acc = fmaf(inrow[i], __ldg(W + i*ED + k), acc);
    out[k] = acc;
}

// ---------------- kernel 3: pi matrix -> rule_mask + reg partials -----------
__global__ void pi_kernel(const float* __restrict__ fc4w, const float* __restrict__ fc4b)
{
    int r = blockIdx.x;
    int tid = threadIdx.x, lane = tid&31, w = tid>>5;
    __shared__ float rarow[ED], f4s[ED];
    if (tid < ED){ rarow[tid] = g_ra[r*ED+tid]; f4s[tid] = fc4w[tid]; }
    __syncthreads();
    float fb4 = fc4b[0];
    float mask_s = 0.f, reg_s = 0.f;
    for (int pp=0; pp<32; pp++){
        int p = w*32 + pp;
        float s = 0.f;
        #pragma unroll
        for (int q=0;q<4;q++){
            int i = lane*4 + q;
            float h = fmaxf(g_propa[p*ED + i] + rarow[i], 0.f);
            s = fmaf(h, f4s[i], s);
        }
        #pragma unroll
        for (int o=16;o>0;o>>=1) s += __shfl_xor_sync(0xffffffffu, s, o);
        if (lane==0){
            float piv = 1.f/(1.f+expf(-(s+fb4)));
            if (piv > 0.5f) mask_s += piv;
            float diag = (r==p) ? 1.f : 0.f;
            float rv = piv*diag + (1.f-piv)*(1.f-diag);
            reg_s += -logf(rv + 1e-8f) * ((1.f-diag) + diag*(float)RULENUM);
        }
    }
    __shared__ float ms[8], rs[8];
    if (lane==0){ ms[w]=mask_s; rs[w]=reg_s; }
    __syncthreads();
    if (tid==0){
        float m=0.f, rg=0.f;
        #pragma unroll
        for (int i=0;i<8;i++){ m+=ms[i]; rg+=rs[i]; }
        g_rulemask[r] = m + 1.f;
        g_regpart[r]  = rg;
    }
}

// ---------------- kernel 4: main (b,r) scoring -------------------------------
// One 128-thread block per (r,b). Thread k owns output dim k.
// fc6 column k in 64 f32x2 registers. j processed in PAIRS:
//   - one __syncthreads per 2 j (4 ping-pong h3 buffers)
//   - shared reads as LDS.128 (ulonglong2 -> 2 f32x2 per load)
//   - 8 independent FMA2 accumulator chains
//   - TRUNCATED shuffle reduction: 3 butterfly steps only; lanes 0-3 hold the
//     4 class partials of all 4 values and store float4s; the last 2 levels
//     happen once in the deferred epilogue.
__global__ void __launch_bounds__(128, 2) main_kernel(
    const int* __restrict__ samemask, const int* __restrict__ padmask,
    const float* __restrict__ fc4w, const float* __restrict__ fc4b,
    const float* __restrict__ fc5w, const float* __restrict__ fc5b,
    const float* __restrict__ fc6w, const float* __restrict__ fc6b)
{
    int r = blockIdx.x, b = blockIdx.y;
    int k = threadIdx.x, lane = k&31, w = k>>5;

    __shared__ __align__(16) float h3sh[4][ED];
    __shared__ __align__(16) float4 sred[MAXPV][16];   // [j][warp*4+class] = {r0,r1,r2,r3}
    __shared__ float scj[MAXPV];

    // pack fc6 column k: Wp[i] = (fc6w[2i][k], fc6w[2i+1][k])
    unsigned long long Wp[ED/2];
    #pragma unroll
    for (int i=0;i<ED/2;i++){
        float lo = fc6w[(2*i)*ED + k];
        float hi = fc6w[(2*i+1)*ED + k];
        PACK2(Wp[i], lo, hi);
    }

    float ra_k = g_ra[r*ED+k], rb_k = g_rb[r*ED+k], rc_k = g_rc[r*ED+k];
    float f4 = fc4w[k], f5 = fc5w[k], b6 = fc6b[k];

    #pragma unroll 1
    for (int jj=0; jj<MAXPV; jj+=2){
        int buf = (jj>>1) & 1;            // buffers {2*buf, 2*buf+1}
        int base0 = (b*MAXPV + jj)*ED + k;
        int base1 = base0 + ED;
        float pa0 = g_pa[base0], pb0 = g_pb[base0], pc0 = g_pc[base0], v0 = g_vemb[base0];
        float pa1 = g_pa[base1], pb1 = g_pb[base1], pc1 = g_pc[base1], v1 = g_vemb[base1];
        float h1_0 = fmaxf(pa0 + ra_k, 0.f), h2_0 = fmaxf(pb0 + rb_k, 0.f);
        float h1_1 = fmaxf(pa1 + ra_k, 0.f), h2_1 = fmaxf(pb1 + rb_k, 0.f);
        h3sh[2*buf  ][k] = fmaxf(pc0 + rc_k, 0.f);
        h3sh[2*buf+1][k] = fmaxf(pc1 + rc_k, 0.f);
        float r0_0 = h1_0*f4, r1_0 = h2_0*f5;
        float r0_1 = h1_1*f4, r1_1 = h2_1*f5;
        __syncthreads();   // publish both h3 buffers; fences reuse from jj-4

        const ulonglong2* hp0 = reinterpret_cast<const ulonglong2*>(h3sh[2*buf  ]);
        const ulonglong2* hp1 = reinterpret_cast<const ulonglong2*>(h3sh[2*buf+1]);
        unsigned long long a0=0ull,a1=0ull,a2=0ull,a3=0ull;
        unsigned long long c0=0ull,c1=0ull,c2=0ull,c3=0ull;
        #pragma unroll
        for (int i=0;i<32;i+=2){
            ulonglong2 t0 = hp0[i];
            ulonglong2 t1 = hp0[i+1];
            ulonglong2 u0 = hp1[i];
            ulonglong2 u1 = hp1[i+1];
            FMA2(a0, t0.x, Wp[2*i+0]);
            FMA2(a1, t0.y, Wp[2*i+1]);
            FMA2(c0, u0.x, Wp[2*i+0]);
            FMA2(c1, u0.y, Wp[2*i+1]);
            FMA2(a2, t1.x, Wp[2*i+2]);
            FMA2(a3, t1.y, Wp[2*i+3]);
            FMA2(c2, u1.x, Wp[2*i+2]);
            FMA2(c3, u1.y, Wp[2*i+3]);
        }
        unsigned long long s01,s23,s64,q01,q23,q64;
        ADD2(s01,a0,a1); ADD2(s23,a2,a3); ADD2(s64,s01,s23);
        ADD2(q01,c0,c1); ADD2(q23,c2,c3); ADD2(q64,q01,q23);
        float ylo,yhi,zlo,zhi;
        UNPACK2(ylo,yhi,s64); UNPACK2(zlo,zhi,q64);
        float y0 = b6 + (ylo + yhi);
        float y1 = b6 + (zlo + zhi);

        // 8 values, 3 butterfly steps each (o=16,8,4): lane L ends up with the
        // sum over the 8 lanes sharing (L&3). Lanes 0-3 store the partials.
        float w2 = y0*y0, w3 = y0*v0, x2 = y1*y1, x3 = y1*v1;
        #pragma unroll
        for (int o=16;o>=4;o>>=1){
            r0_0 += __shfl_xor_sync(0xffffffffu, r0_0, o);
            r1_0 += __shfl_xor_sync(0xffffffffu, r1_0, o);
            w2   += __shfl_xor_sync(0xffffffffu, w2,   o);
            w3   += __shfl_xor_sync(0xffffffffu, w3,   o);
            r0_1 += __shfl_xor_sync(0xffffffffu, r0_1, o);
            r1_1 += __shfl_xor_sync(0xffffffffu, r1_1, o);
            x2   += __shfl_xor_sync(0xffffffffu, x2,   o);
            x3   += __shfl_xor_sync(0xffffffffu, x3,   o);
        }
        if (lane < 4){
            sred[jj  ][w*4 + lane] = make_float4(r0_0, r1_0, w2, w3);
            sred[jj+1][w*4 + lane] = make_float4(r0_1, r1_1, x2, x3);
        }
    }
    __syncthreads();

    float fb4 = fc4b[0], fb5 = fc5b[0];
    if (k < MAXPV){
        float4 acc = make_float4(0.f,0.f,0.f,0.f);
        #pragma unroll
        for (int i=0;i<16;i++){
            float4 q = sred[k][i];
            acc.x += q.x; acc.y += q.y; acc.z += q.z; acc.w += q.w;
        }
        float s1 = 1.f/(1.f+expf(-(acc.x+fb4)));
        float p  = 1.f/(1.f+expf(-(acc.y+fb5)));
        float yn = sqrtf(acc.z);
        float cosv = acc.w / fmaxf(yn, 1e-8f);   // v_emb unit-norm; gv = y/||y||
        float s2 = 0.5f*cosv + 0.5f;
        float sc = p + (1.f-p)*s2;
        sc = (samemask[b*MAXPV+k]==1) ? (s1*sc) : (1.f - s1);
        sc *= (float)padmask[b*MAXPV+k];
        if (!(s1 > 0.5f)) sc = 0.f;
        scj[k] = sc;
    }
    __syncthreads();
    if (k < 32){
        float s = scj[k];
        if (k + 32 < MAXPV) s += scj[k+32];
        #pragma unroll
        for (int o=16;o>0;o>>=1) s += __shfl_xor_sync(0xffffffffu, s, o);
        if (k==0) g_scores[b*RULENUM + r] = s / g_rulemask[r];
    }
}

// ---------------- kernel 5: deterministic finalize ---------------------------
__global__ void finalize_kernel(float* __restrict__ out, int out_size)
{
    int tid = threadIdx.x, lane = tid&31, w = tid>>5;  // 256 threads, 8 warps
    float rg = g_regpart[tid];
    #pragma unroll
    for (int o=16;o>0;o>>=1) rg += __shfl_xor_sync(0xffffffffu, rg, o);
    __shared__ float rs[8];
    if (lane==0) rs[w] = rg;
    __syncthreads();
    if (tid==0 && out_size > BATCH){
        float t=0.f;
        #pragma unroll
        for (int i=0;i<8;i++) t += rs[i];
        out[BATCH] = t / (float)(RULENUM*RULENUM);
    }
    #pragma unroll
    for (int q=0;q<4;q++){
        int b = w*4 + q;
        float m = -1e30f;
        for (int c=lane;c<RULENUM;c+=32) m = fmaxf(m, g_scores[b*RULENUM+c]);
        #pragma unroll
        for (int o=16;o>0;o>>=1) m = fmaxf(m, __shfl_xor_sync(0xffffffffu, m, o));
        if (lane==0 && b < out_size) out[b] = m;
    }
}

// ---------------- launch -----------------------------------------------------
extern "C" void kernel_launch(void* const* d_in, const int* in_sizes, int n_in,
                              void* d_out, int out_size)
{
    const int*   prop = (const int*)d_in[0];
    const int*   val  = (const int*)d_in[1];
    const int*   same = (const int*)d_in[2];
    const int*   pad  = (const int*)d_in[3];
    const float* rule = (const float*)d_in[4];
    const float* ent  = (const float*)d_in[5];
    const float* fc1w = (const float*)d_in[6];
    const float* fc1b = (const float*)d_in[7];
    const float* fc2w = (const float*)d_in[8];
    const float* fc2b = (const float*)d_in[9];
    const float* fc3w = (const float*)d_in[10];
    const float* fc3b = (const float*)d_in[11];
    const float* fc4w = (const float*)d_in[12];
    const float* fc4b = (const float*)d_in[13];
    const float* fc5w = (const float*)d_in[14];
    const float* fc5b = (const float*)d_in[15];
    const float* fc6w = (const float*)d_in[16];
    const float* fc6b = (const float*)d_in[17];

    norm_gather_kernel<<<2*NPV + 2*RULENUM, 128>>>(prop, val, ent, rule);
    small_gemm_kernel<<<3*NPV + 4*RULENUM, 128>>>(fc1w, fc1b, fc2w, fc2b, fc3w, fc3b);
    pi_kernel<<<RULENUM, 256>>>(fc4w, fc4b);
    main_kernel<<<dim3(RULENUM, BATCH), 128>>>(same, pad, fc4w, fc4b, fc5w, fc5b, fc6w, fc6b);
    finalize_kernel<<<1, 256>>>((float*)d_out, out_size);
}

// round 6
// speedup vs baseline: 2.2793x; 1.1966x over previous
#include <cuda_runtime.h>
#include <math.h>

#define BATCH 32
#define MAXPV 50
#define RULENUM 256
#define ED 128
#define NPV (BATCH*MAXPV)   // 1600

#define FMA2(acc,a,bb) asm("fma.rn.f32x2 %0, %1, %2, %0;" : "+l"(acc) : "l"(a), "l"(bb))
#define ADD2(d,a,bb)   asm("add.rn.f32x2 %0, %1, %2;" : "=l"(d) : "l"(a), "l"(bb))
#define PACK2(d,lo,hi) asm("mov.b64 %0, {%1,%2};" : "=l"(d) : "f"(lo), "f"(hi))
#define UNPACK2(lo,hi,s) asm("mov.b64 {%0,%1}, %2;" : "=f"(lo), "=f"(hi) : "l"(s))

// ---------------- scratch (device globals; no allocations allowed) ----------
__device__ float g_pemb[NPV*ED];
__device__ float g_vemb[NPV*ED];
__device__ float g_remb[RULENUM*ED];
__device__ float g_propemb[RULENUM*ED];
__device__ float g_pa[NPV*ED];
__device__ float g_pb[NPV*ED];
__device__ float g_pc[NPV*ED];
__device__ float g_ra[RULENUM*ED];
__device__ float g_rb[RULENUM*ED];
__device__ float g_rc[RULENUM*ED];
__device__ float g_propa[RULENUM*ED];
__device__ float g_rulemask[RULENUM];
__device__ float g_regpart[RULENUM];
__device__ float g_scores[BATCH*RULENUM];

// ---------------- kernel 1: gather + l2 normalize ---------------------------
__global__ void norm_gather_kernel(const int* __restrict__ prop,
                                   const int* __restrict__ val,
                                   const float* __restrict__ ent,
                                   const float* __restrict__ rule)
{
    int row = blockIdx.x;
    int k = threadIdx.x;
    const float* src; float* dst;
    if (row < NPV)            { src = ent + (size_t)prop[row]*ED;              dst = g_pemb + row*ED; }
    else if (row < 2*NPV)     { int t=row-NPV;   src = ent + (size_t)val[t]*ED; dst = g_vemb + t*ED; }
    else if (row < 2*NPV+256) { int t=row-2*NPV; src = rule + t*ED;            dst = g_remb + t*ED; }
    else                      { int t=row-2*NPV-256; src = ent + (size_t)t*ED; dst = g_propemb + t*ED; }

    float x = src[k];
    float s = x*x;
    #pragma unroll
    for (int o=16;o>0;o>>=1) s += __shfl_xor_sync(0xffffffffu, s, o);
    __shared__ float ws[4];
    if ((k&31)==0) ws[k>>5] = s;
    __syncthreads();
    float tot = ws[0]+ws[1]+ws[2]+ws[3];
    float n = fmaxf(sqrtf(tot), 1e-12f);
    dst[k] = x / n;
}

// ---------------- kernel 2: all small 128x128 GEMMs -------------------------
__global__ void small_gemm_kernel(const float* __restrict__ fc1w, const float* __restrict__ fc1b,
                                  const float* __restrict__ fc2w, const float* __restrict__ fc2b,
                                  const float* __restrict__ fc3w, const float* __restrict__ fc3b)
{
    int row = blockIdx.x, k = threadIdx.x;
    const float *in, *W; const float* bias = nullptr; float* out;
    if (row < 1600)      { in=g_pemb+row*ED;            W=fc1w;        out=g_pa+row*ED; }
    else if (row < 3200) { int t=row-1600; in=g_pemb+t*ED; W=fc2w;     out=g_pb+t*ED; }
    else if (row < 4800) { int t=row-3200; in=g_pemb+t*ED; W=fc3w;     out=g_pc+t*ED; }
    else if (row < 5056) { int t=row-4800; in=g_remb+t*ED; W=fc1w+ED*ED; bias=fc1b; out=g_ra+t*ED; }
    else if (row < 5312) { int t=row-5056; in=g_remb+t*ED; W=fc2w+ED*ED; bias=fc2b; out=g_rb+t*ED; }
    else if (row < 5568) { int t=row-5312; in=g_remb+t*ED; W=fc3w+ED*ED; bias=fc3b; out=g_rc+t*ED; }
    else                 { int t=row-5568; in=g_propemb+t*ED; W=fc1w;  out=g_propa+t*ED; }

    __shared__ float inrow[ED];
    inrow[k] = in[k];
    __syncthreads();
    float acc = bias ? bias[k] : 0.f;
    #pragma unroll 8
    for (int i=0;i<ED;i++) acc = fmaf(inrow[i], __ldg(W + i*ED + k), acc);
    out[k] = acc;
}

// ---------------- kernel 3: pi matrix -> rule_mask + reg partials -----------
__global__ void pi_kernel(const float* __restrict__ fc4w, const float* __restrict__ fc4b)
{
    int r = blockIdx.x;
    int tid = threadIdx.x, lane = tid&31, w = tid>>5;
    __shared__ float rarow[ED], f4s[ED];
    if (tid < ED){ rarow[tid] = g_ra[r*ED+tid]; f4s[tid] = fc4w[tid]; }
    __syncthreads();
    float fb4 = fc4b[0];
    float mask_s = 0.f, reg_s = 0.f;
    for (int pp=0; pp<32; pp++){
        int p = w*32 + pp;
        float s = 0.f;
        #pragma unroll
        for (int q=0;q<4;q++){
            int i = lane*4 + q;
            float h = fmaxf(g_propa[p*ED + i] + rarow[i], 0.f);
            s = fmaf(h, f4s[i], s);
        }
        #pragma unroll
        for (int o=16;o>0;o>>=1) s += __shfl_xor_sync(0xffffffffu, s, o);
        if (lane==0){
            float piv = 1.f/(1.f+expf(-(s+fb4)));
            if (piv > 0.5f) mask_s += piv;
            float diag = (r==p) ? 1.f : 0.f;
            float rv = piv*diag + (1.f-piv)*(1.f-diag);
            reg_s += -logf(rv + 1e-8f) * ((1.f-diag) + diag*(float)RULENUM);
        }
    }
    __shared__ float ms[8], rs[8];
    if (lane==0){ ms[w]=mask_s; rs[w]=reg_s; }
    __syncthreads();
    if (tid==0){
        float m=0.f, rg=0.f;
        #pragma unroll
        for (int i=0;i<8;i++){ m+=ms[i]; rg+=rs[i]; }
        g_rulemask[r] = m + 1.f;
        g_regpart[r]  = rg;
    }
}

// ---------------- kernel 4: main (b,r) scoring -------------------------------
// One 128-thread block per (r,b).
// Dot-product role: thread t = (kk = t&63, half = t>>6) owns fc6 OUTPUTS kk and
// kk+64 over i-half [64*half, 64*half+64). W regs: 2 x 32 f32x2 = 128 regs.
// Each h3 value read from shared feeds FOUR FMA2 (2 outputs x 2 j) -> LDS
// bytes halved vs R4. Dim-owner role: thread t owns dim t for h1/h2/h3/v.
// i-half partials combined via small shared array (one extra sync per j-pair).
__global__ void __launch_bounds__(128, 2) main_kernel(
    const int* __restrict__ samemask, const int* __restrict__ padmask,
    const float* __restrict__ fc4w, const float* __restrict__ fc4b,
    const float* __restrict__ fc5w, const float* __restrict__ fc5b,
    const float* __restrict__ fc6w, const float* __restrict__ fc6b)
{
    int r = blockIdx.x, b = blockIdx.y;
    int t = threadIdx.x, lane = t&31, w = t>>5;
    int kk = t & 63, half = t >> 6;

    __shared__ __align__(16) float h3sh[2][ED];
    __shared__ unsigned long long part[2][2][64];      // [jpar][half][kk] = (sO1,sO2)
    __shared__ __align__(16) float4 sred[MAXPV][16];   // [j][warp*4+class]
    __shared__ float scj[MAXPV];

    // Wp1: output kk, Wp2: output kk+64; i-range [64*half, 64*half+64)
    unsigned long long Wp1[32], Wp2[32];
    {
        int ibase = half*64;
        #pragma unroll
        for (int m=0;m<32;m++){
            int i = ibase + 2*m;
            float a0 = fc6w[i*ED + kk],     a1 = fc6w[(i+1)*ED + kk];
            float c0 = fc6w[i*ED + kk+64],  c1 = fc6w[(i+1)*ED + kk+64];
            PACK2(Wp1[m], a0, a1);
            PACK2(Wp2[m], c0, c1);
        }
    }

    float ra_k = g_ra[r*ED+t], rb_k = g_rb[r*ED+t], rc_k = g_rc[r*ED+t];
    float f4 = fc4w[t], f5 = fc5w[t], b6 = fc6b[t];

    #pragma unroll 1
    for (int jj=0; jj<MAXPV; jj+=2){
        int base0 = (b*MAXPV + jj)*ED + t;
        int base1 = base0 + ED;
        float pa0 = g_pa[base0], pb0 = g_pb[base0], pc0 = g_pc[base0], v0 = g_vemb[base0];
        float pa1 = g_pa[base1], pb1 = g_pb[base1], pc1 = g_pc[base1], v1 = g_vemb[base1];
        float h1_0 = fmaxf(pa0 + ra_k, 0.f), h2_0 = fmaxf(pb0 + rb_k, 0.f);
        float h1_1 = fmaxf(pa1 + ra_k, 0.f), h2_1 = fmaxf(pb1 + rb_k, 0.f);
        h3sh[0][t] = fmaxf(pc0 + rc_k, 0.f);
        h3sh[1][t] = fmaxf(pc1 + rc_k, 0.f);
        float r0_0 = h1_0*f4, r1_0 = h2_0*f5;
        float r0_1 = h1_1*f4, r1_1 = h2_1*f5;
        __syncthreads();   // publish h3 (both j)

        // dot partials: this thread's i-half (64 floats = 16 x ulonglong2),
        // 2 outputs, both j -> 8 independent FMA2 chains
        const ulonglong2* hp0 = reinterpret_cast<const ulonglong2*>(&h3sh[0][half*64]);
        const ulonglong2* hp1 = reinterpret_cast<const ulonglong2*>(&h3sh[1][half*64]);
        unsigned long long a0=0ull,a1=0ull,b0=0ull,b1=0ull;  // j0: o1, o2
        unsigned long long c0=0ull,c1=0ull,d0=0ull,d1=0ull;  // j1: o1, o2
        #pragma unroll
        for (int q=0;q<16;q++){
            ulonglong2 u = hp0[q];
            ulonglong2 z = hp1[q];
            FMA2(a0, u.x, Wp1[2*q  ]);
            FMA2(b0, u.x, Wp2[2*q  ]);
            FMA2(c0, z.x, Wp1[2*q  ]);
            FMA2(d0, z.x, Wp2[2*q  ]);
            FMA2(a1, u.y, Wp1[2*q+1]);
            FMA2(b1, u.y, Wp2[2*q+1]);
            FMA2(c1, z.y, Wp1[2*q+1]);
            FMA2(d1, z.y, Wp2[2*q+1]);
        }
        unsigned long long sa,sb,sc,sd;
        ADD2(sa,a0,a1); ADD2(sb,b0,b1); ADD2(sc,c0,c1); ADD2(sd,d0,d1);
        float lo,hi, pO1_0,pO2_0,pO1_1,pO2_1;
        UNPACK2(lo,hi,sa); pO1_0 = lo+hi;
        UNPACK2(lo,hi,sb); pO2_0 = lo+hi;
        UNPACK2(lo,hi,sc); pO1_1 = lo+hi;
        UNPACK2(lo,hi,sd); pO2_1 = lo+hi;
        unsigned long long w0p, w1p;
        PACK2(w0p, pO1_0, pO2_0);
        PACK2(w1p, pO1_1, pO2_1);
        part[0][half][kk] = w0p;
        part[1][half][kk] = w1p;
        __syncthreads();   // publish partials

        // combine halves for output dim t
        float e0lo,e0hi,e1lo,e1hi,f0lo,f0hi,f1lo,f1hi;
        UNPACK2(e0lo,e0hi, part[0][0][kk]);
        UNPACK2(e1lo,e1hi, part[0][1][kk]);
        UNPACK2(f0lo,f0hi, part[1][0][kk]);
        UNPACK2(f1lo,f1hi, part[1][1][kk]);
        float p0 = (t < 64) ? (e0lo + e1lo) : (e0hi + e1hi);
        float p1 = (t < 64) ? (f0lo + f1lo) : (f0hi + f1hi);
        float y0 = b6 + p0;
        float y1 = b6 + p1;

        // 8 values, truncated butterfly (o=16,8,4); lanes 0-3 store partials
        float w2 = y0*y0, w3 = y0*v0, x2 = y1*y1, x3 = y1*v1;
        #pragma unroll
        for (int o=16;o>=4;o>>=1){
            r0_0 += __shfl_xor_sync(0xffffffffu, r0_0, o);
            r1_0 += __shfl_xor_sync(0xffffffffu, r1_0, o);
            w2   += __shfl_xor_sync(0xffffffffu, w2,   o);
            w3   += __shfl_xor_sync(0xffffffffu, w3,   o);
            r0_1 += __shfl_xor_sync(0xffffffffu, r0_1, o);
            r1_1 += __shfl_xor_sync(0xffffffffu, r1_1, o);
            x2   += __shfl_xor_sync(0xffffffffu, x2,   o);
            x3   += __shfl_xor_sync(0xffffffffu, x3,   o);
        }
        if (lane < 4){
            sred[jj  ][w*4 + lane] = make_float4(r0_0, r1_0, w2, w3);
            sred[jj+1][w*4 + lane] = make_float4(r0_1, r1_1, x2, x3);
        }
    }
    __syncthreads();

    float fb4 = fc4b[0], fb5 = fc5b[0];
    if (t < MAXPV){
        float4 acc = make_float4(0.f,0.f,0.f,0.f);
        #pragma unroll
        for (int i=0;i<16;i++){
            float4 q = sred[t][i];
            acc.x += q.x; acc.y += q.y; acc.z += q.z; acc.w += q.w;
        }
        float s1 = 1.f/(1.f+expf(-(acc.x+fb4)));
        float p  = 1.f/(1.f+expf(-(acc.y+fb5)));
        float yn = sqrtf(acc.z);
        float cosv = acc.w / fmaxf(yn, 1e-8f);   // v_emb unit-norm; gv = y/||y||
        float s2 = 0.5f*cosv + 0.5f;
        float sc = p + (1.f-p)*s2;
        sc = (samemask[b*MAXPV+t]==1) ? (s1*sc) : (1.f - s1);
        sc *= (float)padmask[b*MAXPV+t];
        if (!(s1 > 0.5f)) sc = 0.f;
        scj[t] = sc;
    }
    __syncthreads();
    if (t < 32){
        float s = scj[t];
        if (t + 32 < MAXPV) s += scj[t+32];
        #pragma unroll
        for (int o=16;o>0;o>>=1) s += __shfl_xor_sync(0xffffffffu, s, o);
        if (t==0) g_scores[b*RULENUM + r] = s / g_rulemask[r];
    }
}

// ---------------- kernel 5: deterministic finalize ---------------------------
__global__ void finalize_kernel(float* __restrict__ out, int out_size)
{
    int tid = threadIdx.x, lane = tid&31, w = tid>>5;  // 256 threads, 8 warps
    float rg = g_regpart[tid];
    #pragma unroll
    for (int o=16;o>0;o>>=1) rg += __shfl_xor_sync(0xffffffffu, rg, o);
    __shared__ float rs[8];
    if (lane==0) rs[w] = rg;
    __syncthreads();
    if (tid==0 && out_size > BATCH){
        float t=0.f;
        #pragma unroll
        for (int i=0;i<8;i++) t += rs[i];
        out[BATCH] = t / (float)(RULENUM*RULENUM);
    }
    #pragma unroll
    for (int q=0;q<4;q++){
        int b = w*4 + q;
        float m = -1e30f;
        for (int c=lane;c<RULENUM;c+=32) m = fmaxf(m, g_scores[b*RULENUM+c]);
        #pragma unroll
        for (int o=16;o>0;o>>=1) m = fmaxf(m, __shfl_xor_sync(0xffffffffu, m, o));
        if (lane==0 && b < out_size) out[b] = m;
    }
}

// ---------------- launch -----------------------------------------------------
extern "C" void kernel_launch(void* const* d_in, const int* in_sizes, int n_in,
                              void* d_out, int out_size)
{
    const int*   prop = (const int*)d_in[0];
    const int*   val  = (const int*)d_in[1];
    const int*   same = (const int*)d_in[2];
    const int*   pad  = (const int*)d_in[3];
    const float* rule = (const float*)d_in[4];
    const float* ent  = (const float*)d_in[5];
    const float* fc1w = (const float*)d_in[6];
    const float* fc1b = (const float*)d_in[7];
    const float* fc2w = (const float*)d_in[8];
    const float* fc2b = (const float*)d_in[9];
    const float* fc3w = (const float*)d_in[10];
    const float* fc3b = (const float*)d_in[11];
    const float* fc4w = (const float*)d_in[12];
    const float* fc4b = (const float*)d_in[13];
    const float* fc5w = (const float*)d_in[14];
    const float* fc5b = (const float*)d_in[15];
    const float* fc6w = (const float*)d_in[16];
    const float* fc6b = (const float*)d_in[17];

    norm_gather_kernel<<<2*NPV + 2*RULENUM, 128>>>(prop, val, ent, rule);
    small_gemm_kernel<<<3*NPV + 4*RULENUM, 128>>>(fc1w, fc1b, fc2w, fc2b, fc3w, fc3b);
    pi_kernel<<<RULENUM, 256>>>(fc4w, fc4b);
    main_kernel<<<dim3(RULENUM, BATCH), 128>>>(same, pad, fc4w, fc4b, fc5w, fc5b, fc6w, fc6b);
    finalize_kernel<<<1, 256>>>((float*)d_out, out_size);
}